// round 11
// baseline (speedup 1.0000x reference)
#include <cuda_runtime.h>
#include <cuda_bf16.h>
#include <stdint.h>

#define N_TOK 65536
#define D     256
#define K     1024
#define BCH   64              // codes per chunk
#define NCH   (K / BCH)       // 16 chunks
#define CAP   16
#define WINDOW 2e-5f          // >= 2x worst-case split-MMA error (~5e-6)
#define APITCH 264            // bf16 pitch: 528B -> conflict-free frag loads

// Scratch (no cudaMalloc allowed)
__device__ float g_counts[K];
__device__ float g_dw[K * D];
__device__ float g_cs[K];
__device__ unsigned long long g_loss;
__device__ __nv_bfloat16 g_xh[(size_t)N_TOK * D];
__device__ __nv_bfloat16 g_xl[(size_t)N_TOK * D];
__device__ __nv_bfloat16 g_cbh[K * D];
__device__ __nv_bfloat16 g_cbl[K * D];

__device__ __forceinline__ unsigned fkey(float f) {
    unsigned b = __float_as_uint(f);
    return (b & 0x80000000u) ? ~b : (b ^ 0x80000000u);
}
__device__ __forceinline__ float fkeyinv(unsigned k) {
    unsigned b = (k & 0x80000000u) ? (k ^ 0x80000000u) : ~k;
    return __uint_as_float(b);
}

struct SmemT {
    __nv_bfloat16 Ah[128 * APITCH];   // 67584 B
    __nv_bfloat16 Al[128 * APITCH];   // 67584 B
    __nv_bfloat16 Bh[BCH * APITCH];   // 33792 B
    __nv_bfloat16 Bl[BCH * APITCH];   // 33792 B
    float cssm[K];
    float rxs[128];
    unsigned runmin[128];
    int candn[128];
    unsigned short cand[128][CAP];
    int bestI[128];
    float bestD[128];
};                                    // ~213.5 KB

// ---------------------------------------------------------------------------
__global__ void vq_prep() {
    int i = blockIdx.x * blockDim.x + threadIdx.x;
    if (i < K * D) g_dw[i] = 0.0f;
    if (i < K)     g_counts[i] = 0.0f;
    if (i == 0)    g_loss = 0ull;
}

// fp32 -> (hi, lo) bf16 split. lo = bf16(x - float(hi)) ; x-hi exact (Sterbenz).
__global__ void vq_cvt2(const float* __restrict__ src,
                        __nv_bfloat16* __restrict__ hi,
                        __nv_bfloat16* __restrict__ lo) {
    size_t i = ((size_t)blockIdx.x * blockDim.x + threadIdx.x) * 8;
    float x[8];
    *(float4*)(x)     = *(const float4*)(src + i);
    *(float4*)(x + 4) = *(const float4*)(src + i + 4);
    __nv_bfloat16 h[8], l[8];
    #pragma unroll
    for (int j = 0; j < 8; j++) {
        h[j] = __float2bfloat16_rn(x[j]);
        l[j] = __float2bfloat16_rn(x[j] - __bfloat162float(h[j]));
    }
    *(uint4*)(hi + i) = *(uint4*)h;
    *(uint4*)(lo + i) = *(uint4*)l;
}

// Codebook squared norms (exact fp32)
__global__ void vq_cs(const float* __restrict__ CB) {
    int w = (blockIdx.x * blockDim.x + threadIdx.x) >> 5;
    int lane = threadIdx.x & 31;
    if (w >= K) return;
    const float* row = CB + (size_t)w * D + lane * 8;
    float4 v0 = *(const float4*)row;
    float4 v1 = *(const float4*)(row + 4);
    float s = v0.x * v0.x + v0.y * v0.y + v0.z * v0.z + v0.w * v0.w
            + v1.x * v1.x + v1.y * v1.y + v1.z * v1.z + v1.w * v1.w;
    #pragma unroll
    for (int o = 16; o > 0; o >>= 1) s += __shfl_xor_sync(0xffffffffu, s, o);
    if (lane == 0) g_cs[w] = s;
}

// ---------------------------------------------------------------------------
// Main: split-bf16 MMA scores + provable candidate set + exact rescore
// Block: 256 thr = 8 warps, 2(M)x4(N). 128 tokens vs all K codes (16x64).
// ---------------------------------------------------------------------------
__global__ __launch_bounds__(256, 1) void vq_dist(
    const float* __restrict__ X, const float* __restrict__ CB,
    float* __restrict__ outQ, float* __restrict__ outIdx)
{
    extern __shared__ SmemT sm[];
    SmemT& s = sm[0];
    const int tid  = threadIdx.x;
    const int lane = tid & 31;
    const int wid  = tid >> 5;
    const int mw   = wid >> 2;       // 0..1 : 64 token-rows each
    const int nw   = wid & 3;        // 0..3 : 16 code-cols each
    const int g    = lane >> 2;      // 0..7
    const int tg2  = (lane & 3) << 1;
    const int tok0 = blockIdx.x * 128;

    if (tid < 128) { s.runmin[tid] = 0xFFFFFFFFu; s.candn[tid] = 0; }
    for (int i = tid; i < K; i += 256) s.cssm[i] = g_cs[i];

    // Stage A hi/lo (128 tokens x 256 bf16 each)
    {
        int row = tid >> 1, half = tid & 1;
        size_t off = (size_t)(tok0 + row) * D + half * 128;
        const uint4* sh = (const uint4*)(g_xh + off);
        const uint4* sl = (const uint4*)(g_xl + off);
        #pragma unroll
        for (int j = 0; j < 16; j++) {
            *(uint4*)&s.Ah[row * APITCH + half * 128 + j * 8] = sh[j];
            *(uint4*)&s.Al[row * APITCH + half * 128 + j * 8] = sl[j];
        }
    }
    // Exact per-token ||x||^2 (same summation order as passing rounds)
    if (tid < 128) {
        const float* xr = X + (size_t)(tok0 + tid) * D;
        float acc = 0.f;
        #pragma unroll 8
        for (int j = 0; j < D; j += 4) {
            float4 v = *(const float4*)(xr + j);
            acc += v.x * v.x; acc += v.y * v.y; acc += v.z * v.z; acc += v.w * v.w;
        }
        s.rxs[tid] = acc;
    }

    for (int ch = 0; ch < NCH; ch++) {
        __syncthreads();
        // Stage B chunk hi/lo (64 codes x 256 bf16)
        {
            int row = tid >> 2, q = tid & 3;
            size_t off = (size_t)(ch * BCH + row) * D + q * 64;
            const uint4* sh = (const uint4*)(g_cbh + off);
            const uint4* sl = (const uint4*)(g_cbl + off);
            #pragma unroll
            for (int j = 0; j < 8; j++) {
                *(uint4*)&s.Bh[row * APITCH + q * 64 + j * 8] = sh[j];
                *(uint4*)&s.Bl[row * APITCH + q * 64 + j * 8] = sl[j];
            }
        }
        __syncthreads();

        float acc[4][2][4];
        #pragma unroll
        for (int mt = 0; mt < 4; mt++)
            #pragma unroll
            for (int nt = 0; nt < 2; nt++)
                #pragma unroll
                for (int q = 0; q < 4; q++) acc[mt][nt][q] = 0.f;

        // Three passes: xh*ch + xl*ch + xh*cl, shared fp32 accumulator
        #pragma unroll 1
        for (int p = 0; p < 3; p++) {
            const __nv_bfloat16* A_ = (p == 1) ? s.Al : s.Ah;
            const __nv_bfloat16* B_ = (p == 2) ? s.Bl : s.Bh;
            #pragma unroll 2
            for (int dd = 0; dd < D; dd += 16) {
                int kk = dd + tg2;
                uint32_t a[4][4];
                #pragma unroll
                for (int mt = 0; mt < 4; mt++) {
                    int r0 = mw * 64 + mt * 16 + g;
                    a[mt][0] = *(const uint32_t*)&A_[r0 * APITCH + kk];
                    a[mt][1] = *(const uint32_t*)&A_[(r0 + 8) * APITCH + kk];
                    a[mt][2] = *(const uint32_t*)&A_[r0 * APITCH + kk + 8];
                    a[mt][3] = *(const uint32_t*)&A_[(r0 + 8) * APITCH + kk + 8];
                }
                #pragma unroll
                for (int nt = 0; nt < 2; nt++) {
                    int c0 = nw * 16 + nt * 8 + g;
                    uint32_t b0 = *(const uint32_t*)&B_[c0 * APITCH + kk];
                    uint32_t b1 = *(const uint32_t*)&B_[c0 * APITCH + kk + 8];
                    #pragma unroll
                    for (int mt = 0; mt < 4; mt++) {
                        asm volatile(
                            "mma.sync.aligned.m16n8k16.row.col.f32.bf16.bf16.f32 "
                            "{%0,%1,%2,%3}, {%4,%5,%6,%7}, {%8,%9}, {%0,%1,%2,%3};"
                            : "+f"(acc[mt][nt][0]), "+f"(acc[mt][nt][1]),
                              "+f"(acc[mt][nt][2]), "+f"(acc[mt][nt][3])
                            : "r"(a[mt][0]), "r"(a[mt][1]), "r"(a[mt][2]), "r"(a[mt][3]),
                              "r"(b0), "r"(b1));
                    }
                }
            }
        }

        // Per-row running minima of e = cs - 2*s~  (rx row-constant: dropped)
        #pragma unroll
        for (int mt = 0; mt < 4; mt++) {
            float v0 = 3.4e38f, v1 = 3.4e38f;
            #pragma unroll
            for (int nt = 0; nt < 2; nt++) {
                int c0 = ch * BCH + nw * 16 + nt * 8 + tg2;
                float cs0 = s.cssm[c0], cs1 = s.cssm[c0 + 1];
                v0 = fminf(v0, fminf(cs0 - 2.f * acc[mt][nt][0], cs1 - 2.f * acc[mt][nt][1]));
                v1 = fminf(v1, fminf(cs0 - 2.f * acc[mt][nt][2], cs1 - 2.f * acc[mt][nt][3]));
            }
            #pragma unroll
            for (int off = 1; off <= 2; off <<= 1) {
                v0 = fminf(v0, __shfl_xor_sync(0xffffffffu, v0, off));
                v1 = fminf(v1, __shfl_xor_sync(0xffffffffu, v1, off));
            }
            if ((lane & 3) == 0) {
                int r0 = mw * 64 + mt * 16 + g;
                atomicMin(&s.runmin[r0], fkey(v0));
                atomicMin(&s.runmin[r0 + 8], fkey(v1));
            }
        }
        __syncthreads();

        // Collect candidates within WINDOW of running min (provable superset)
        #pragma unroll
        for (int mt = 0; mt < 4; mt++) {
            int r0 = mw * 64 + mt * 16 + g;
            float thr0 = fkeyinv(s.runmin[r0]) + WINDOW;
            float thr1 = fkeyinv(s.runmin[r0 + 8]) + WINDOW;
            #pragma unroll
            for (int nt = 0; nt < 2; nt++) {
                int c0 = ch * BCH + nw * 16 + nt * 8 + tg2;
                float cs0 = s.cssm[c0], cs1 = s.cssm[c0 + 1];
                float e00 = cs0 - 2.f * acc[mt][nt][0];
                float e01 = cs1 - 2.f * acc[mt][nt][1];
                float e10 = cs0 - 2.f * acc[mt][nt][2];
                float e11 = cs1 - 2.f * acc[mt][nt][3];
                if (e00 <= thr0) { int p = atomicAdd(&s.candn[r0], 1);     if (p < CAP) s.cand[r0][p]     = (unsigned short)c0; }
                if (e01 <= thr0) { int p = atomicAdd(&s.candn[r0], 1);     if (p < CAP) s.cand[r0][p]     = (unsigned short)(c0 + 1); }
                if (e10 <= thr1) { int p = atomicAdd(&s.candn[r0 + 8], 1); if (p < CAP) s.cand[r0 + 8][p] = (unsigned short)c0; }
                if (e11 <= thr1) { int p = atomicAdd(&s.candn[r0 + 8], 1); if (p < CAP) s.cand[r0 + 8][p] = (unsigned short)(c0 + 1); }
            }
        }
    }
    __syncthreads();

    // Exact fp32 rescore of candidates (warp per token; deterministic winner)
    for (int i = 0; i < 16; i++) {
        int t = wid * 16 + i;
        const float* xr = X + (size_t)(tok0 + t) * D + lane * 8;
        float4 xa = *(const float4*)xr;
        float4 xb = *(const float4*)(xr + 4);
        int nc = s.candn[t];
        bool full = (nc > CAP);
        int n = full ? K : nc;
        float rx = s.rxs[t];
        float best = 3.4e38f; int bk = K;
        for (int j = 0; j < n; j++) {
            int k = full ? j : (int)s.cand[t][j];
            const float* cr = CB + (size_t)k * D + lane * 8;
            float4 ca = *(const float4*)cr;
            float4 cb = *(const float4*)(cr + 4);
            float v = xa.x * ca.x;
            v = fmaf(xa.y, ca.y, v); v = fmaf(xa.z, ca.z, v); v = fmaf(xa.w, ca.w, v);
            v = fmaf(xb.x, cb.x, v); v = fmaf(xb.y, cb.y, v);
            v = fmaf(xb.z, cb.z, v); v = fmaf(xb.w, cb.w, v);
            #pragma unroll
            for (int o = 16; o > 0; o >>= 1) v += __shfl_xor_sync(0xffffffffu, v, o);
            float d = (rx + s.cssm[k]) - 2.f * v;
            if (d < best || (d == best && k < bk)) { best = d; bk = k; }
        }
        if (lane == 0) {
            s.bestI[t] = bk; s.bestD[t] = best;
            outIdx[tok0 + t] = (float)bk;
        }
    }
    __syncthreads();

    if (tid < 128) atomicAdd(&g_counts[s.bestI[tid]], 1.0f);
    if (tid == 0) {
        double sum = 0.0;
        for (int r = 0; r < 128; r++) sum += (double)s.bestD[r];
        atomicAdd(&g_loss, (unsigned long long)llrint(sum * 1048576.0));
    }
    __syncthreads();

    // Gather quantized rows + scatter dw
    for (int i = tid; i < 128 * (D / 4); i += 256) {
        int row = i >> 6;
        int c4  = (i & 63) << 2;
        int b   = s.bestI[row];
        float4 q = *(const float4*)(CB + (size_t)b * D + c4);
        *(float4*)(outQ + (size_t)(tok0 + row) * D + c4) = q;
        float4 xv = *(const float4*)(X + (size_t)(tok0 + row) * D + c4);
        float* dwp = g_dw + (size_t)b * D + c4;
        atomicAdd(dwp + 0, xv.x);
        atomicAdd(dwp + 1, xv.y);
        atomicAdd(dwp + 2, xv.z);
        atomicAdd(dwp + 3, xv.w);
    }
}

// ---------------------------------------------------------------------------
__global__ void vq_finalize(const float* __restrict__ ecs,
                            float* __restrict__ out_cs,
                            float* __restrict__ out_perp,
                            float* __restrict__ out_loss)
{
    __shared__ float sbuf[K];
    int k = threadIdx.x;
    float cnt = g_counts[k];
    float cn = 0.99f * ecs[k] + 0.01f * cnt;

    sbuf[k] = cn;
    __syncthreads();
    for (int st = K / 2; st > 0; st >>= 1) {
        if (k < st) sbuf[k] += sbuf[k + st];
        __syncthreads();
    }
    float ntot = sbuf[0];
    __syncthreads();

    out_cs[k] = (cn + 1e-5f) / (ntot + 0.01024f) * ntot;

    float p = cnt * (1.0f / 65536.0f);
    sbuf[k] = p * logf(p + 1e-10f);
    __syncthreads();
    for (int st = K / 2; st > 0; st >>= 1) {
        if (k < st) sbuf[k] += sbuf[k + st];
        __syncthreads();
    }
    if (k == 0) {
        out_perp[0] = expf(-sbuf[0]);
        double loss = (double)g_loss * (1.0 / 1048576.0) / (65536.0 * 256.0);
        out_loss[0] = 0.25f * (float)loss;
    }
}

__global__ void vq_ema(const float* __restrict__ emaw,
                       const float* __restrict__ ncs,
                       float* __restrict__ outE,
                       float* __restrict__ outW)
{
    int i = blockIdx.x * blockDim.x + threadIdx.x;
    float w = 0.99f * emaw[i] + 0.01f * g_dw[i];
    outE[i] = w;
    outW[i] = w / ncs[i >> 8];
}

// ---------------------------------------------------------------------------
extern "C" void kernel_launch(void* const* d_in, const int* in_sizes, int n_in,
                              void* d_out, int out_size)
{
    const float* X   = (const float*)d_in[0];
    const float* CB  = (const float*)d_in[1];
    const float* ECS = (const float*)d_in[2];
    const float* EW  = (const float*)d_in[3];
    float* out = (float*)d_out;

    const size_t OQ = 0;
    const size_t OL = (size_t)N_TOK * D;
    const size_t OI = OL + 1;
    const size_t OP = OI + N_TOK;
    const size_t OC = OP + 1;
    const size_t OE = OC + K;
    const size_t OW = OE + (size_t)K * D;

    // Idempotent; called every time (no static guards per harness rules)
    cudaFuncSetAttribute(vq_dist, cudaFuncAttributeMaxDynamicSharedMemorySize,
                         (int)sizeof(SmemT));

    vq_prep<<<(K * D + 255) / 256, 256>>>();
    vq_cvt2<<<(N_TOK * D / 8) / 256, 256>>>(X, g_xh, g_xl);
    vq_cvt2<<<(K * D / 8) / 256, 256>>>(CB, g_cbh, g_cbl);
    vq_cs<<<K / 8, 256>>>(CB);
    vq_dist<<<N_TOK / 128, 256, sizeof(SmemT)>>>(X, CB, out + OQ, out + OI);
    vq_finalize<<<1, K>>>(ECS, out + OC, out + OP, out + OL);
    vq_ema<<<(K * D) / 256, 256>>>(EW, out + OC, out + OE, out + OW);
}

// round 13
// speedup vs baseline: 1.2317x; 1.2317x over previous
#include <cuda_runtime.h>
#include <stdint.h>

#define N_TOK 65536
#define D     256
#define DW    (D / 4)          // 64 words per row
#define K     1024
#define NB    128              // codes per chunk
#define NCHUNK (K / NB)        // 8
#define CAP   16
#define WINDOW 2e-3f

// Scratch (no cudaMalloc allowed)
__device__ float g_counts[K];
__device__ float g_dw[K * D];
__device__ float g_cs[K];
__device__ unsigned long long g_loss;
__device__ uint32_t g_qx[(size_t)N_TOK * DW];   // int8-packed tokens
__device__ uint32_t g_qc[K * DW];               // int8-packed codebook
__device__ float g_sx[N_TOK];                   // token quant scales
__device__ float g_sc[K];                       // code quant scales

__device__ __forceinline__ unsigned fkey(float f) {
    unsigned b = __float_as_uint(f);
    return (b & 0x80000000u) ? ~b : (b ^ 0x80000000u);
}
__device__ __forceinline__ float fkeyinv(unsigned k) {
    unsigned b = (k & 0x80000000u) ? (k ^ 0x80000000u) : ~k;
    return __uint_as_float(b);
}

struct SmemT {
    uint32_t At[DW * 128];        // word-transposed: At[kw*128 + row]
    uint32_t Bt[DW * 128];        // Bt[kw*128 + code]
    float cssm[K];                // exact ||c||^2
    float scsm[K];                // code quant scales
    float sxs[128];               // token quant scales
    float rxs[128];               // exact ||x||^2
    unsigned runmin[128];
    int candn[128];
    unsigned short cand[128][CAP];
    int bestI[128];
    float bestD[128];
};                                // ~80.9 KB -> 2 CTAs/SM

// ---------------------------------------------------------------------------
__global__ void vq_prep() {
    int i = blockIdx.x * blockDim.x + threadIdx.x;
    if (i < K * D) g_dw[i] = 0.0f;
    if (i < K)     g_counts[i] = 0.0f;
    if (i == 0)    g_loss = 0ull;
}

// Symmetric int8 quantization, one warp per row of 256 floats
__global__ void vq_quant(const float* __restrict__ src,
                         uint32_t* __restrict__ q,
                         float* __restrict__ scale, int rows) {
    int row = blockIdx.x * 8 + (threadIdx.x >> 5);
    int lane = threadIdx.x & 31;
    if (row >= rows) return;
    const float* xr = src + (size_t)row * D + lane * 8;
    float x[8];
    *(float4*)(x)     = *(const float4*)xr;
    *(float4*)(x + 4) = *(const float4*)(xr + 4);
    float am = 0.f;
    #pragma unroll
    for (int j = 0; j < 8; j++) am = fmaxf(am, fabsf(x[j]));
    #pragma unroll
    for (int o = 16; o > 0; o >>= 1) am = fmaxf(am, __shfl_xor_sync(0xffffffffu, am, o));
    float inv = (am > 0.f) ? 127.f / am : 0.f;
    float s   = (am > 0.f) ? am / 127.f : 0.f;
    uint32_t w0 = 0, w1 = 0;
    #pragma unroll
    for (int j = 0; j < 4; j++) {
        int qv = __float2int_rn(x[j] * inv);
        qv = max(-127, min(127, qv));
        w0 |= ((uint32_t)qv & 255u) << (j * 8);
    }
    #pragma unroll
    for (int j = 0; j < 4; j++) {
        int qv = __float2int_rn(x[4 + j] * inv);
        qv = max(-127, min(127, qv));
        w1 |= ((uint32_t)qv & 255u) << (j * 8);
    }
    uint2 o; o.x = w0; o.y = w1;
    *(uint2*)(q + (size_t)row * DW + lane * 2) = o;
    if (lane == 0) scale[row] = s;
}

// Codebook squared norms (exact fp32)
__global__ void vq_cs(const float* __restrict__ CB) {
    int w = (blockIdx.x * blockDim.x + threadIdx.x) >> 5;
    int lane = threadIdx.x & 31;
    if (w >= K) return;
    const float* row = CB + (size_t)w * D + lane * 8;
    float4 v0 = *(const float4*)row;
    float4 v1 = *(const float4*)(row + 4);
    float s = v0.x * v0.x + v0.y * v0.y + v0.z * v0.z + v0.w * v0.w
            + v1.x * v1.x + v1.y * v1.y + v1.z * v1.z + v1.w * v1.w;
    #pragma unroll
    for (int o = 16; o > 0; o >>= 1) s += __shfl_xor_sync(0xffffffffu, s, o);
    if (lane == 0) g_cs[w] = s;
}

// ---------------------------------------------------------------------------
// Main: dp4a int8 scores + provable candidate window + exact fp32 rescore
// 256 thr; thread (ty=tid>>4, tx=tid&15) owns an 8x8 (token x code) tile.
// ---------------------------------------------------------------------------
__global__ __launch_bounds__(256, 2) void vq_dist(
    const float* __restrict__ X, const float* __restrict__ CB,
    float* __restrict__ outQ, float* __restrict__ outIdx)
{
    extern __shared__ char dsm[];
    SmemT& s = *(SmemT*)dsm;
    const int tid  = threadIdx.x;
    const int lane = tid & 31;
    const int wid  = tid >> 5;
    const int tx   = tid & 15;
    const int ty   = tid >> 4;
    const int tok0 = blockIdx.x * 128;

    if (tid < 128) { s.runmin[tid] = 0xFFFFFFFFu; s.candn[tid] = 0; }
    for (int i = tid; i < K; i += 256) { s.cssm[i] = g_cs[i]; s.scsm[i] = g_sc[i]; }
    if (tid < 128) s.sxs[tid] = g_sx[tok0 + tid];

    // Stage A (word-transposed int8 tokens)
    {
        int row = tid >> 1, half = tid & 1;
        const uint4* src = (const uint4*)(g_qx + (size_t)(tok0 + row) * DW + half * 32);
        #pragma unroll
        for (int j = 0; j < 8; j++) {
            uint4 v = src[j];
            int w = half * 32 + j * 4;
            s.At[(w + 0) * 128 + row] = v.x;
            s.At[(w + 1) * 128 + row] = v.y;
            s.At[(w + 2) * 128 + row] = v.z;
            s.At[(w + 3) * 128 + row] = v.w;
        }
    }
    // Exact per-token ||x||^2 (same order as passing rounds)
    if (tid < 128) {
        const float* xr = X + (size_t)(tok0 + tid) * D;
        float acc = 0.f;
        #pragma unroll 8
        for (int j = 0; j < D; j += 4) {
            float4 v = *(const float4*)(xr + j);
            acc += v.x * v.x; acc += v.y * v.y; acc += v.z * v.z; acc += v.w * v.w;
        }
        s.rxs[tid] = acc;
    }

    for (int ch = 0; ch < NCHUNK; ch++) {
        __syncthreads();
        // Stage B chunk (word-transposed int8 codes)
        {
            int row = tid >> 1, half = tid & 1;
            const uint4* src = (const uint4*)(g_qc + (size_t)(ch * NB + row) * DW + half * 32);
            #pragma unroll
            for (int j = 0; j < 8; j++) {
                uint4 v = src[j];
                int w = half * 32 + j * 4;
                s.Bt[(w + 0) * 128 + row] = v.x;
                s.Bt[(w + 1) * 128 + row] = v.y;
                s.Bt[(w + 2) * 128 + row] = v.z;
                s.Bt[(w + 3) * 128 + row] = v.w;
            }
        }
        __syncthreads();

        int acc[8][8];
        #pragma unroll
        for (int r = 0; r < 8; r++)
            #pragma unroll
            for (int c = 0; c < 8; c++) acc[r][c] = 0;

        #pragma unroll 2
        for (int kw = 0; kw < DW; kw++) {
            uint32_t av[8], bv[8];
            *(uint4*)(av)     = *(const uint4*)&s.At[kw * 128 + ty * 8];
            *(uint4*)(av + 4) = *(const uint4*)&s.At[kw * 128 + ty * 8 + 4];
            *(uint4*)(bv)     = *(const uint4*)&s.Bt[kw * 128 + tx * 8];
            *(uint4*)(bv + 4) = *(const uint4*)&s.Bt[kw * 128 + tx * 8 + 4];
            #pragma unroll
            for (int r = 0; r < 8; r++)
                #pragma unroll
                for (int c = 0; c < 8; c++)
                    acc[r][c] = __dp4a((int)av[r], (int)bv[c], acc[r][c]);
        }

        // e = cs - 2*sx*sc*dp ; per-row chunk min -> smem runmin
        float sc8[8], cs8[8];
        #pragma unroll
        for (int c = 0; c < 8; c++) {
            int code = ch * NB + tx * 8 + c;
            sc8[c] = s.scsm[code];
            cs8[c] = s.cssm[code];
        }
        float eF[8][8];
        #pragma unroll
        for (int r = 0; r < 8; r++) {
            float m = -2.f * s.sxs[ty * 8 + r];
            float rmin = 3.4e38f;
            #pragma unroll
            for (int c = 0; c < 8; c++) {
                float e = fmaf(m * sc8[c], (float)acc[r][c], cs8[c]);
                eF[r][c] = e;
                rmin = fminf(rmin, e);
            }
            #pragma unroll
            for (int o = 1; o <= 8; o <<= 1)
                rmin = fminf(rmin, __shfl_xor_sync(0xffffffffu, rmin, o));
            if ((lane & 15) == 0) atomicMin(&s.runmin[ty * 8 + r], fkey(rmin));
        }
        __syncthreads();

        // Collect candidates within WINDOW of the running min (superset proof:
        // runmin only decreases, so e <= final_min + W  =>  e <= cur_min + W)
        #pragma unroll
        for (int r = 0; r < 8; r++) {
            int row = ty * 8 + r;
            float thr = fkeyinv(s.runmin[row]) + WINDOW;
            #pragma unroll
            for (int c = 0; c < 8; c++) {
                if (eF[r][c] <= thr) {
                    int p = atomicAdd(&s.candn[row], 1);
                    if (p < CAP) s.cand[row][p] = (unsigned short)(ch * NB + tx * 8 + c);
                }
            }
        }
    }
    __syncthreads();

    // Exact fp32 rescore (warp per token, 16 tokens/warp; deterministic winner)
    for (int i = 0; i < 16; i++) {
        int t = wid * 16 + i;
        const float* xr = X + (size_t)(tok0 + t) * D + lane * 8;
        float4 xa = *(const float4*)xr;
        float4 xb = *(const float4*)(xr + 4);
        int nc = s.candn[t];
        bool full = (nc > CAP);
        int n = full ? K : nc;
        float rx = s.rxs[t];
        float best = 3.4e38f; int bk = K;
        for (int j = 0; j < n; j++) {
            int k = full ? j : (int)s.cand[t][j];
            const float* cr = CB + (size_t)k * D + lane * 8;
            float4 ca = *(const float4*)cr;
            float4 cb = *(const float4*)(cr + 4);
            float v = xa.x * ca.x;
            v = fmaf(xa.y, ca.y, v); v = fmaf(xa.z, ca.z, v); v = fmaf(xa.w, ca.w, v);
            v = fmaf(xb.x, cb.x, v); v = fmaf(xb.y, cb.y, v);
            v = fmaf(xb.z, cb.z, v); v = fmaf(xb.w, cb.w, v);
            #pragma unroll
            for (int o = 16; o > 0; o >>= 1) v += __shfl_xor_sync(0xffffffffu, v, o);
            float d = (rx + s.cssm[k]) - 2.f * v;
            if (d < best || (d == best && k < bk)) { best = d; bk = k; }
        }
        if (lane == 0) {
            s.bestI[t] = bk; s.bestD[t] = best;
            outIdx[tok0 + t] = (float)bk;
        }
    }
    __syncthreads();

    if (tid < 128) atomicAdd(&g_counts[s.bestI[tid]], 1.0f);
    if (tid == 0) {
        double sum = 0.0;
        for (int r = 0; r < 128; r++) sum += (double)s.bestD[r];
        atomicAdd(&g_loss, (unsigned long long)llrint(sum * 1048576.0));
    }
    __syncthreads();

    // Gather quantized rows + scatter dw
    for (int i = tid; i < 128 * (D / 4); i += 256) {
        int row = i >> 6;
        int c4  = (i & 63) << 2;
        int b   = s.bestI[row];
        float4 q = *(const float4*)(CB + (size_t)b * D + c4);
        *(float4*)(outQ + (size_t)(tok0 + row) * D + c4) = q;
        float4 xv = *(const float4*)(X + (size_t)(tok0 + row) * D + c4);
        float* dwp = g_dw + (size_t)b * D + c4;
        atomicAdd(dwp + 0, xv.x);
        atomicAdd(dwp + 1, xv.y);
        atomicAdd(dwp + 2, xv.z);
        atomicAdd(dwp + 3, xv.w);
    }
}

// ---------------------------------------------------------------------------
__global__ void vq_finalize(const float* __restrict__ ecs,
                            float* __restrict__ out_cs,
                            float* __restrict__ out_perp,
                            float* __restrict__ out_loss)
{
    __shared__ float sbuf[K];
    int k = threadIdx.x;
    float cnt = g_counts[k];
    float cn = 0.99f * ecs[k] + 0.01f * cnt;

    sbuf[k] = cn;
    __syncthreads();
    for (int st = K / 2; st > 0; st >>= 1) {
        if (k < st) sbuf[k] += sbuf[k + st];
        __syncthreads();
    }
    float ntot = sbuf[0];
    __syncthreads();

    out_cs[k] = (cn + 1e-5f) / (ntot + 0.01024f) * ntot;

    float p = cnt * (1.0f / 65536.0f);
    sbuf[k] = p * logf(p + 1e-10f);
    __syncthreads();
    for (int st = K / 2; st > 0; st >>= 1) {
        if (k < st) sbuf[k] += sbuf[k + st];
        __syncthreads();
    }
    if (k == 0) {
        out_perp[0] = expf(-sbuf[0]);
        double loss = (double)g_loss * (1.0 / 1048576.0) / (65536.0 * 256.0);
        out_loss[0] = 0.25f * (float)loss;
    }
}

__global__ void vq_ema(const float* __restrict__ emaw,
                       const float* __restrict__ ncs,
                       float* __restrict__ outE,
                       float* __restrict__ outW)
{
    int i = blockIdx.x * blockDim.x + threadIdx.x;
    float w = 0.99f * emaw[i] + 0.01f * g_dw[i];
    outE[i] = w;
    outW[i] = w / ncs[i >> 8];
}

// ---------------------------------------------------------------------------
extern "C" void kernel_launch(void* const* d_in, const int* in_sizes, int n_in,
                              void* d_out, int out_size)
{
    const float* X   = (const float*)d_in[0];
    const float* CB  = (const float*)d_in[1];
    const float* ECS = (const float*)d_in[2];
    const float* EW  = (const float*)d_in[3];
    float* out = (float*)d_out;

    const size_t OQ = 0;
    const size_t OL = (size_t)N_TOK * D;
    const size_t OI = OL + 1;
    const size_t OP = OI + N_TOK;
    const size_t OC = OP + 1;
    const size_t OE = OC + K;
    const size_t OW = OE + (size_t)K * D;

    cudaFuncSetAttribute(vq_dist, cudaFuncAttributeMaxDynamicSharedMemorySize,
                         (int)sizeof(SmemT));

    vq_prep<<<(K * D + 255) / 256, 256>>>();
    vq_quant<<<N_TOK / 8, 256>>>(X, g_qx, g_sx, N_TOK);
    vq_quant<<<K / 8, 256>>>(CB, g_qc, g_sc, K);
    vq_cs<<<K / 8, 256>>>(CB);
    vq_dist<<<N_TOK / 128, 256, sizeof(SmemT)>>>(X, CB, out + OQ, out + OI);
    vq_finalize<<<1, K>>>(ECS, out + OC, out + OP, out + OL);
    vq_ema<<<(K * D) / 256, 256>>>(EW, out + OC, out + OE, out + OW);
}